// round 14
// baseline (speedup 1.0000x reference)
#include <cuda_runtime.h>
#include <cuda_fp16.h>
#include <cstdint>

// Causal attention, warp-level fp16 mma.sync flash-attention, round 14:
// r11 inner kernel verbatim + fine task split (max 8 key-tiles, 40 tasks/bh)
// + SEPARATE variable-part combine kernel (no device-side tickets — r13's
// fused combine had a replay race).
// B=4, H=8, S=2048, D=64.

#define S_LEN 2048
#define BM 128
#define BN 64
#define HD 64
#define NT 128
#define QSC 0.18033688011112042f   /* 0.125 * log2(e) */
#define KST 72                     /* padded halves per SMEM row (144 B) */
#define TOT (4*8*2048*64)
#define KVB 9216                   /* one K or V tile buffer: 64*72*2 bytes */

__device__ __align__(16) __half KHg[TOT];
__device__ __align__(16) __half VHg[TOT];
__device__ __align__(16) float OPg[32 * 36 * (BM * HD)];   // split partials (36 segs/bh)
__device__ __align__(16) float LPg[32 * 36 * BM];          // split row-sums

// segment base offsets within a bh for qt=4..15 (parts: 2,2,2,2,3,3,3,3,4,4,4,4)
__device__ const int PBASE[12] = {0, 2, 4, 6, 8, 11, 14, 17, 20, 24, 28, 32};

// task table: {qt, kt0, kt1, part(-1 = unsplit)}, sorted by cost desc (max 8 tiles)
__device__ const int4 TASKS[40] = {
    // cost 8
    { 7,  0,  7, 0}, { 7,  8, 15, 1},
    {10,  0,  7, 0},
    {11,  0,  7, 0}, {11,  8, 15, 1}, {11, 16, 23, 2},
    {14,  0,  7, 0}, {14,  8, 15, 1},
    {15,  0,  7, 0}, {15,  8, 15, 1}, {15, 16, 23, 2}, {15, 24, 31, 3},
    { 3,  0,  7, -1},
    // cost 7
    { 6,  0,  6, 0}, { 6,  7, 13, 1},
    { 9,  0,  6, 0}, { 9,  7, 13, 1},
    {10,  8, 14, 1}, {10, 15, 21, 2},
    {12,  0,  6, 0}, {12,  7, 13, 1},
    {13,  0,  6, 0}, {13,  7, 13, 1}, {13, 14, 20, 2}, {13, 21, 27, 3},
    {14, 16, 22, 2}, {14, 23, 29, 3},
    // cost 6
    { 5,  0,  5, 0}, { 5,  6, 11, 1},
    { 8,  0,  5, 0}, { 8,  6, 11, 1}, { 8, 12, 17, 2},
    { 9, 14, 19, 2},
    {12, 14, 19, 2}, {12, 20, 25, 3},
    { 2,  0,  5, -1},
    // cost 5
    { 4,  0,  4, 0}, { 4,  5,  9, 1},
    // cost 4, 2
    { 1,  0,  3, -1}, { 0,  0,  1, -1}
};

// ---- prepass: fp32 -> fp16 for K and V (once) ----
__global__ __launch_bounds__(256)
void conv_kv(const float* __restrict__ K, const float* __restrict__ V) {
    int i = (blockIdx.x * 256 + threadIdx.x) * 8;
    float4 a = *reinterpret_cast<const float4*>(K + i);
    float4 b = *reinterpret_cast<const float4*>(K + i + 4);
    __half2 h[4] = { __floats2half2_rn(a.x, a.y), __floats2half2_rn(a.z, a.w),
                     __floats2half2_rn(b.x, b.y), __floats2half2_rn(b.z, b.w) };
    *reinterpret_cast<float4*>(&KHg[i]) = *reinterpret_cast<const float4*>(h);
    a = *reinterpret_cast<const float4*>(V + i);
    b = *reinterpret_cast<const float4*>(V + i + 4);
    __half2 g[4] = { __floats2half2_rn(a.x, a.y), __floats2half2_rn(a.z, a.w),
                     __floats2half2_rn(b.x, b.y), __floats2half2_rn(b.z, b.w) };
    *reinterpret_cast<float4*>(&VHg[i]) = *reinterpret_cast<const float4*>(g);
}

__device__ __forceinline__ void ldsm_x4(uint32_t* r, uint32_t a) {
    asm volatile("ldmatrix.sync.aligned.m8n8.x4.shared.b16 {%0,%1,%2,%3}, [%4];"
                 : "=r"(r[0]), "=r"(r[1]), "=r"(r[2]), "=r"(r[3]) : "r"(a));
}
__device__ __forceinline__ void ldsm_x4t(uint32_t* r, uint32_t a) {
    asm volatile("ldmatrix.sync.aligned.m8n8.x4.trans.shared.b16 {%0,%1,%2,%3}, [%4];"
                 : "=r"(r[0]), "=r"(r[1]), "=r"(r[2]), "=r"(r[3]) : "r"(a));
}
__device__ __forceinline__ void mma16816(float* c, const uint32_t* a, uint32_t b0, uint32_t b1) {
    asm volatile("mma.sync.aligned.m16n8k16.row.col.f32.f16.f16.f32 "
        "{%0,%1,%2,%3}, {%4,%5,%6,%7}, {%8,%9}, {%0,%1,%2,%3};"
        : "+f"(c[0]), "+f"(c[1]), "+f"(c[2]), "+f"(c[3])
        : "r"(a[0]), "r"(a[1]), "r"(a[2]), "r"(a[3]), "r"(b0), "r"(b1));
}
__device__ __forceinline__ uint32_t exph2(float s1, float s0) {
    uint32_t d;
    asm("{\n\t.reg .b32 t;\n\t"
        "cvt.rn.f16x2.f32 t, %1, %2;\n\t"
        "ex2.approx.f16x2 %0, t;\n\t}"
        : "=r"(d) : "f"(s1), "f"(s0));
    return d;
}
__device__ __forceinline__ void cp16(uint32_t dst, const void* src) {
    asm volatile("cp.async.cg.shared.global [%0], [%1], 16;" :: "r"(dst), "l"(src) : "memory");
}
#define CP_COMMIT() asm volatile("cp.async.commit_group;" ::: "memory")
#define CP_WAIT(n)  asm volatile("cp.async.wait_group %0;" :: "n"(n) : "memory")

// dynamic smem layout (bytes)
#define SM_Q   0                    /* 128*72*2 = 18432 */
#define SM_K   18432                /* 3 * KVB = 27648 */
#define SM_V   46080                /* 3 * KVB = 27648 */
#define SM_TOTAL 73984              /* +256 pad: ones-block ldsm tail overread */

__global__ __launch_bounds__(NT, 3)
void fa_hmma12(const float* __restrict__ Q, float* __restrict__ O)
{
    extern __shared__ char smem[];
    __half* Qs = reinterpret_cast<__half*>(smem + SM_Q);

    const int tid = threadIdx.x;
    const int w = tid >> 5, lane = tid & 31;
    const int g = lane >> 3, r8 = lane & 7;
    const int bh = blockIdx.x;
    const int4 tk = TASKS[blockIdx.y];
    const int qt = tk.x, kt0 = tk.y, kt1 = tk.z, part = tk.w;
    const int q0 = qt * BM;

    const size_t base = (size_t)bh * S_LEN * HD;
    const float* Qb = Q + base;
    const __half* KH = KHg + base;
    const __half* VH = VHg + base;
    float* Ob = O + base;

    const uint32_t sb32 = (uint32_t)__cvta_generic_to_shared(smem);
    const uint32_t kb32 = sb32 + SM_K;
    const uint32_t vb32 = sb32 + SM_V;

    // ---- init ones-column (col 64 = 1.0, 65..71 = 0) in all 3 V buffers ----
    for (int idx = tid; idx < 192; idx += NT) {
        int b = idx >> 6, r = idx & 63;
        *reinterpret_cast<uint4*>(smem + SM_V + b * KVB + r * (KST * 2) + 128) =
            make_uint4(0x00003C00u, 0u, 0u, 0u);
    }

    // cp.async: 512 16B-chunks per tile per tensor, 4 per thread
    uint32_t kd[4]; int cro[4], cco[4];
    #pragma unroll
    for (int i = 0; i < 4; i++) {
        int c = tid + i * NT;
        cro[i] = c >> 3; cco[i] = (c & 7) << 3;
        kd[i] = (uint32_t)(cro[i] * KST + cco[i]) * 2;
    }

    // ---- prologue: issue tiles kt0 and kt0+1 (every task has >= 2 tiles) ----
    {
        const __half* ks = KH + (size_t)kt0 * BN * HD;
        const __half* vs = VH + (size_t)kt0 * BN * HD;
        #pragma unroll
        for (int i = 0; i < 4; i++) {
            cp16(kb32 + (uint32_t)(kt0 % 3) * KVB + kd[i], ks + cro[i] * HD + cco[i]);
            cp16(vb32 + (uint32_t)(kt0 % 3) * KVB + kd[i], vs + cro[i] * HD + cco[i]);
        }
        CP_COMMIT();
        ks += (size_t)BN * HD; vs += (size_t)BN * HD;
        #pragma unroll
        for (int i = 0; i < 4; i++) {
            cp16(kb32 + (uint32_t)((kt0 + 1) % 3) * KVB + kd[i], ks + cro[i] * HD + cco[i]);
            cp16(vb32 + (uint32_t)((kt0 + 1) % 3) * KVB + kd[i], vs + cro[i] * HD + cco[i]);
        }
        CP_COMMIT();
    }

    // ---- load Q tile, pre-scaled, fp32 -> fp16 ----
    #pragma unroll
    for (int it = 0; it < 16; it++) {
        int i = tid + it * NT;
        int r = i >> 4, c = (i & 15) << 2;
        float4 v = *reinterpret_cast<const float4*>(Qb + (size_t)(q0 + r) * HD + c);
        half2* dst = reinterpret_cast<half2*>(&Qs[r * KST + c]);
        dst[0] = __floats2half2_rn(v.x * QSC, v.y * QSC);
        dst[1] = __floats2half2_rn(v.z * QSC, v.w * QSC);
    }
    __syncthreads();

    // ---- Q A-fragments in registers: 2 row-blocks of 16 ----
    uint32_t qa[2][4][4];
    #pragma unroll
    for (int rb = 0; rb < 2; rb++) {
        int row = w * 32 + rb * 16 + (g & 1) * 8 + r8;
        #pragma unroll
        for (int kb = 0; kb < 4; kb++) {
            int colh = kb * 16 + (g >> 1) * 8;
            ldsm_x4(qa[rb][kb], sb32 + (uint32_t)(row * KST + colh) * 2);
        }
    }

    float o[2][8][4];
    #pragma unroll
    for (int rb = 0; rb < 2; rb++)
        #pragma unroll
        for (int a = 0; a < 8; a++)
            #pragma unroll
            for (int b = 0; b < 4; b++) o[rb][a][b] = 0.f;
    float ol[2][4];
    #pragma unroll
    for (int rb = 0; rb < 2; rb++)
        #pragma unroll
        for (int b = 0; b < 4; b++) ol[rb][b] = 0.f;

    const int qgA = q0 + w * 32 + (lane >> 2);
    const uint32_t koff = (uint32_t)(((g & 1) * 8 + r8) * KST + (g >> 1) * 8) * 2;

    for (int kt = kt0; kt <= kt1; kt++) {
        const int k0 = kt * BN;
        CP_WAIT(1);            // tile kt resident
        __syncthreads();       // buffer (kt+2)%3 free

        // ---- issue tile kt+2 ----
        {
            int kn = min(kt + 2, kt1) * BN;
            uint32_t bo = (uint32_t)((kt + 2) % 3) * KVB;
            const __half* ks = KH + (size_t)kn * HD;
            const __half* vs = VH + (size_t)kn * HD;
            #pragma unroll
            for (int i = 0; i < 4; i++) {
                cp16(kb32 + bo + kd[i], ks + cro[i] * HD + cco[i]);
                cp16(vb32 + bo + kd[i], vs + cro[i] * HD + cco[i]);
            }
            CP_COMMIT();
        }

        const uint32_t kbase = kb32 + (uint32_t)(kt % 3) * KVB;
        const uint32_t vbase = vb32 + (uint32_t)(kt % 3) * KVB;
        const bool dg = (kt >= 2 * qt);

        // ---- two 32-column halves: QK -> exp -> PV (r11 structure, verbatim) ----
        #pragma unroll
        for (int hf = 0; hf < 2; hf++) {
            float sacc[2][4][4];
            #pragma unroll
            for (int rb = 0; rb < 2; rb++)
                #pragma unroll
                for (int a = 0; a < 4; a++)
                    #pragma unroll
                    for (int b = 0; b < 4; b++) sacc[rb][a][b] = 0.f;

            #pragma unroll
            for (int kb = 0; kb < 4; kb++) {
                #pragma unroll
                for (int nbp = 0; nbp < 2; nbp++) {
                    uint32_t bk[4];
                    ldsm_x4(bk, kbase + koff +
                            (uint32_t)(((hf * 2 + nbp) * 16) * KST + kb * 16) * 2);
                    #pragma unroll
                    for (int rb = 0; rb < 2; rb++) {
                        mma16816(sacc[rb][2 * nbp],     qa[rb][kb], bk[0], bk[2]);
                        mma16816(sacc[rb][2 * nbp + 1], qa[rb][kb], bk[1], bk[3]);
                    }
                }
            }

            uint32_t ph[2][4][2];
            #pragma unroll
            for (int rb = 0; rb < 2; rb++) {
                #pragma unroll
                for (int nb = 0; nb < 4; nb++) {
                    float s0 = sacc[rb][nb][0], s1 = sacc[rb][nb][1];
                    float s2 = sacc[rb][nb][2], s3 = sacc[rb][nb][3];
                    if (dg) {
                        int c0 = k0 + hf * 32 + nb * 8 + ((lane & 3) << 1);
                        int r0 = qgA + rb * 16;
                        if (c0     > r0)     s0 = -30000.f;
                        if (c0 + 1 > r0)     s1 = -30000.f;
                        if (c0     > r0 + 8) s2 = -30000.f;
                        if (c0 + 1 > r0 + 8) s3 = -30000.f;
                    }
                    ph[rb][nb][0] = exph2(s1, s0);
                    ph[rb][nb][1] = exph2(s3, s2);
                }
            }

            #pragma unroll
            for (int kbl = 0; kbl < 2; kbl++) {
                int kbk = hf * 2 + kbl;
                #pragma unroll
                for (int nbp = 0; nbp < 4; nbp++) {
                    uint32_t bv[4];
                    ldsm_x4t(bv, vbase + koff +
                             (uint32_t)(kbk * 16 * KST + nbp * 16) * 2);
                    #pragma unroll
                    for (int rb = 0; rb < 2; rb++) {
                        uint32_t pa[4] = { ph[rb][2 * kbl][0], ph[rb][2 * kbl][1],
                                           ph[rb][2 * kbl + 1][0], ph[rb][2 * kbl + 1][1] };
                        mma16816(o[rb][2 * nbp],     pa, bv[0], bv[1]);
                        mma16816(o[rb][2 * nbp + 1], pa, bv[2], bv[3]);
                    }
                }
                uint32_t bo1[4];
                ldsm_x4t(bo1, vbase + koff + (uint32_t)(kbk * 16 * KST + 64) * 2);
                #pragma unroll
                for (int rb = 0; rb < 2; rb++) {
                    uint32_t pa[4] = { ph[rb][2 * kbl][0], ph[rb][2 * kbl][1],
                                       ph[rb][2 * kbl + 1][0], ph[rb][2 * kbl + 1][1] };
                    mma16816(ol[rb], pa, bo1[0], bo1[1]);
                }
            }
        }
    }
    CP_WAIT(0);

    if (part < 0) {
        // ---- unsplit: normalize and store directly ----
        #pragma unroll
        for (int rb = 0; rb < 2; rb++) {
            const float l0 = __shfl_sync(0xffffffffu, ol[rb][0], lane & 28);
            const float l1 = __shfl_sync(0xffffffffu, ol[rb][2], lane & 28);
            const float inv0 = 1.f / l0;
            const float inv1 = 1.f / l1;
            const int row0 = q0 + w * 32 + rb * 16 + (lane >> 2);
            const int colb = (lane & 3) << 1;
            #pragma unroll
            for (int nb = 0; nb < 8; nb++) {
                int col = nb * 8 + colb;
                *reinterpret_cast<float2*>(Ob + (size_t)row0 * HD + col) =
                    make_float2(o[rb][nb][0] * inv0, o[rb][nb][1] * inv0);
                *reinterpret_cast<float2*>(Ob + (size_t)(row0 + 8) * HD + col) =
                    make_float2(o[rb][nb][2] * inv1, o[rb][nb][3] * inv1);
            }
        }
    } else {
        // ---- split: write unnormalized partials + row sums ----
        const int qi = qt - 4;
        const int sid = bh * 36 + PBASE[qi] + part;
        float* op = OPg + (size_t)sid * (BM * HD);
        float* lp = LPg + (size_t)sid * BM;
        #pragma unroll
        for (int rb = 0; rb < 2; rb++) {
            const int row0 = w * 32 + rb * 16 + (lane >> 2);
            const int colb = (lane & 3) << 1;
            #pragma unroll
            for (int nb = 0; nb < 8; nb++) {
                int col = nb * 8 + colb;
                *reinterpret_cast<float2*>(op + row0 * HD + col) =
                    make_float2(o[rb][nb][0], o[rb][nb][1]);
                *reinterpret_cast<float2*>(op + (row0 + 8) * HD + col) =
                    make_float2(o[rb][nb][2], o[rb][nb][3]);
            }
            if ((lane & 3) == 0) {
                lp[row0]     = __shfl_sync(0xffffffffu, ol[rb][0], lane);
                lp[row0 + 8] = __shfl_sync(0xffffffffu, ol[rb][2], lane);
            }
        }
    }
}

// ---- combine: O = (sum_p P_p) / (sum_p l_p) for split q-tiles (qt 4..15) ----
__global__ __launch_bounds__(128)
void fa_combine(float* __restrict__ O) {
    int t = blockIdx.x * 128 + threadIdx.x;    // 393216 threads x 8 floats
    int e = t * 8;
    int tile = e >> 13;                         // 0..383 = bh*12 + qi
    int rem = e & 8191;
    int bh = tile / 12, qi = tile % 12;
    int parts = 2 + (qi >= 4) + (qi >= 8);
    int pb = bh * 36 + PBASE[qi];
    int row = rem >> 6;
    float l = 0.f;
    float4 a0 = make_float4(0.f, 0.f, 0.f, 0.f);
    float4 a1 = make_float4(0.f, 0.f, 0.f, 0.f);
    for (int p = 0; p < parts; p++) {
        const float* pp = OPg + (size_t)(pb + p) * (BM * HD) + rem;
        float4 v = reinterpret_cast<const float4*>(pp)[0];
        a0.x += v.x; a0.y += v.y; a0.z += v.z; a0.w += v.w;
        v = reinterpret_cast<const float4*>(pp)[1];
        a1.x += v.x; a1.y += v.y; a1.z += v.z; a1.w += v.w;
        l += LPg[(size_t)(pb + p) * BM + row];
    }
    float inv = 1.f / l;
    float* out = O + (size_t)bh * S_LEN * HD + (size_t)(qi + 4) * BM * HD + rem;
    reinterpret_cast<float4*>(out)[0] =
        make_float4(a0.x * inv, a0.y * inv, a0.z * inv, a0.w * inv);
    reinterpret_cast<float4*>(out)[1] =
        make_float4(a1.x * inv, a1.y * inv, a1.z * inv, a1.w * inv);
}

extern "C" void kernel_launch(void* const* d_in, const int* in_sizes, int n_in,
                              void* d_out, int out_size) {
    const float* Q = (const float*)d_in[0];
    const float* K = (const float*)d_in[1];
    const float* V = (const float*)d_in[2];
    float* O = (float*)d_out;
    (void)in_sizes; (void)n_in; (void)out_size;

    conv_kv<<<TOT / (256 * 8), 256>>>(K, V);

    cudaFuncSetAttribute(fa_hmma12, cudaFuncAttributeMaxDynamicSharedMemorySize, SM_TOTAL);
    dim3 grid(32, 40);                 // x = bh, y = task (heavy-first, max 8 tiles)
    fa_hmma12<<<grid, NT, SM_TOTAL>>>(Q, O);

    fa_combine<<<3072, 128>>>(O);      // 32*12 split tiles, variable parts
}

// round 15
// speedup vs baseline: 1.1391x; 1.1391x over previous
#include <cuda_runtime.h>
#include <cuda_fp16.h>
#include <cstdint>

// Causal attention, warp-level fp16 mma.sync flash-attention, round 15:
// r11 EXACTLY (best: 68.1us = prepass 9.3 + main ~55 + combine ~3.5)
// with one change: high-MLP prepass (16 floats/tensor/thread, all loads
// issued before stores) -> prepass ~6us.
// B=4, H=8, S=2048, D=64.

#define S_LEN 2048
#define BM 128
#define BN 64
#define HD 64
#define NT 128
#define QSC 0.18033688011112042f   /* 0.125 * log2(e) */
#define KST 72                     /* padded halves per SMEM row (144 B) */
#define TOT (4*8*2048*64)
#define KVB 9216                   /* one K or V tile buffer: 64*72*2 bytes */

__device__ __align__(16) __half KHg[TOT];
__device__ __align__(16) __half VHg[TOT];
__device__ __align__(16) float OPg[32 * 8 * 2 * (BM * HD)];  // split partials
__device__ __align__(16) float LPg[32 * 8 * 2 * BM];         // split row-sums

// task table: {qt, kt0, kt1, part(-1 = unsplit)} sorted by cost desc (r11)
__device__ const int4 TASKS[24] = {
    { 7,  0, 15, -1}, {15,  0, 15,  0}, {15, 16, 31,  1},
    {14,  0, 14,  0}, {14, 15, 29,  1},
    { 6,  0, 13, -1}, {13,  0, 13,  0}, {13, 14, 27,  1},
    {12,  0, 12,  0}, {12, 13, 25,  1},
    { 5,  0, 11, -1}, {11,  0, 11,  0}, {11, 12, 23,  1},
    {10,  0, 10,  0}, {10, 11, 21,  1},
    { 4,  0,  9, -1}, { 9,  0,  9,  0}, { 9, 10, 19,  1},
    { 8,  0,  8,  0}, { 8,  9, 17,  1},
    { 3,  0,  7, -1}, { 2,  0,  5, -1}, { 1,  0,  3, -1}, { 0,  0,  1, -1}
};

// ---- prepass: fp32 -> fp16, 16 floats per tensor per thread, MLP=8 ----
__global__ __launch_bounds__(256)
void conv_kv(const float* __restrict__ K, const float* __restrict__ V) {
    int i = (blockIdx.x * 256 + threadIdx.x) * 16;
    // issue all 8 independent loads first
    float4 k0 = *reinterpret_cast<const float4*>(K + i);
    float4 k1 = *reinterpret_cast<const float4*>(K + i + 4);
    float4 k2 = *reinterpret_cast<const float4*>(K + i + 8);
    float4 k3 = *reinterpret_cast<const float4*>(K + i + 12);
    float4 v0 = *reinterpret_cast<const float4*>(V + i);
    float4 v1 = *reinterpret_cast<const float4*>(V + i + 4);
    float4 v2 = *reinterpret_cast<const float4*>(V + i + 8);
    float4 v3 = *reinterpret_cast<const float4*>(V + i + 12);
    __half2 h0[4] = { __floats2half2_rn(k0.x, k0.y), __floats2half2_rn(k0.z, k0.w),
                      __floats2half2_rn(k1.x, k1.y), __floats2half2_rn(k1.z, k1.w) };
    __half2 h1[4] = { __floats2half2_rn(k2.x, k2.y), __floats2half2_rn(k2.z, k2.w),
                      __floats2half2_rn(k3.x, k3.y), __floats2half2_rn(k3.z, k3.w) };
    __half2 g0[4] = { __floats2half2_rn(v0.x, v0.y), __floats2half2_rn(v0.z, v0.w),
                      __floats2half2_rn(v1.x, v1.y), __floats2half2_rn(v1.z, v1.w) };
    __half2 g1[4] = { __floats2half2_rn(v2.x, v2.y), __floats2half2_rn(v2.z, v2.w),
                      __floats2half2_rn(v3.x, v3.y), __floats2half2_rn(v3.z, v3.w) };
    *reinterpret_cast<float4*>(&KHg[i])     = *reinterpret_cast<const float4*>(h0);
    *reinterpret_cast<float4*>(&KHg[i + 8]) = *reinterpret_cast<const float4*>(h1);
    *reinterpret_cast<float4*>(&VHg[i])     = *reinterpret_cast<const float4*>(g0);
    *reinterpret_cast<float4*>(&VHg[i + 8]) = *reinterpret_cast<const float4*>(g1);
}

__device__ __forceinline__ void ldsm_x4(uint32_t* r, uint32_t a) {
    asm volatile("ldmatrix.sync.aligned.m8n8.x4.shared.b16 {%0,%1,%2,%3}, [%4];"
                 : "=r"(r[0]), "=r"(r[1]), "=r"(r[2]), "=r"(r[3]) : "r"(a));
}
__device__ __forceinline__ void ldsm_x4t(uint32_t* r, uint32_t a) {
    asm volatile("ldmatrix.sync.aligned.m8n8.x4.trans.shared.b16 {%0,%1,%2,%3}, [%4];"
                 : "=r"(r[0]), "=r"(r[1]), "=r"(r[2]), "=r"(r[3]) : "r"(a));
}
__device__ __forceinline__ void mma16816(float* c, const uint32_t* a, uint32_t b0, uint32_t b1) {
    asm volatile("mma.sync.aligned.m16n8k16.row.col.f32.f16.f16.f32 "
        "{%0,%1,%2,%3}, {%4,%5,%6,%7}, {%8,%9}, {%0,%1,%2,%3};"
        : "+f"(c[0]), "+f"(c[1]), "+f"(c[2]), "+f"(c[3])
        : "r"(a[0]), "r"(a[1]), "r"(a[2]), "r"(a[3]), "r"(b0), "r"(b1));
}
__device__ __forceinline__ uint32_t exph2(float s1, float s0) {
    uint32_t d;
    asm("{\n\t.reg .b32 t;\n\t"
        "cvt.rn.f16x2.f32 t, %1, %2;\n\t"
        "ex2.approx.f16x2 %0, t;\n\t}"
        : "=r"(d) : "f"(s1), "f"(s0));
    return d;
}
__device__ __forceinline__ void cp16(uint32_t dst, const void* src) {
    asm volatile("cp.async.cg.shared.global [%0], [%1], 16;" :: "r"(dst), "l"(src) : "memory");
}
#define CP_COMMIT() asm volatile("cp.async.commit_group;" ::: "memory")
#define CP_WAIT(n)  asm volatile("cp.async.wait_group %0;" :: "n"(n) : "memory")

// dynamic smem layout (bytes)
#define SM_Q   0                    /* 128*72*2 = 18432 */
#define SM_K   18432                /* 3 * KVB = 27648 */
#define SM_V   46080                /* 3 * KVB = 27648 */
#define SM_TOTAL 73984              /* +256 pad: ones-block ldsm tail overread */

__global__ __launch_bounds__(NT, 3)
void fa_hmma13(const float* __restrict__ Q, float* __restrict__ O)
{
    extern __shared__ char smem[];
    __half* Qs = reinterpret_cast<__half*>(smem + SM_Q);

    const int tid = threadIdx.x;
    const int w = tid >> 5, lane = tid & 31;
    const int g = lane >> 3, r8 = lane & 7;
    const int bh = blockIdx.x;
    const int4 tk = TASKS[blockIdx.y];
    const int qt = tk.x, kt0 = tk.y, kt1 = tk.z, part = tk.w;
    const int q0 = qt * BM;

    const size_t base = (size_t)bh * S_LEN * HD;
    const float* Qb = Q + base;
    const __half* KH = KHg + base;
    const __half* VH = VHg + base;
    float* Ob = O + base;

    const uint32_t sb32 = (uint32_t)__cvta_generic_to_shared(smem);
    const uint32_t kb32 = sb32 + SM_K;
    const uint32_t vb32 = sb32 + SM_V;

    // ---- init ones-column (col 64 = 1.0, 65..71 = 0) in all 3 V buffers ----
    for (int idx = tid; idx < 192; idx += NT) {
        int b = idx >> 6, r = idx & 63;
        *reinterpret_cast<uint4*>(smem + SM_V + b * KVB + r * (KST * 2) + 128) =
            make_uint4(0x00003C00u, 0u, 0u, 0u);
    }

    // cp.async: 512 16B-chunks per tile per tensor, 4 per thread
    uint32_t kd[4]; int cro[4], cco[4];
    #pragma unroll
    for (int i = 0; i < 4; i++) {
        int c = tid + i * NT;
        cro[i] = c >> 3; cco[i] = (c & 7) << 3;
        kd[i] = (uint32_t)(cro[i] * KST + cco[i]) * 2;
    }

    // ---- prologue: issue tiles kt0 and kt0+1 (every task has >= 2 tiles) ----
    {
        const __half* ks = KH + (size_t)kt0 * BN * HD;
        const __half* vs = VH + (size_t)kt0 * BN * HD;
        #pragma unroll
        for (int i = 0; i < 4; i++) {
            cp16(kb32 + (uint32_t)(kt0 % 3) * KVB + kd[i], ks + cro[i] * HD + cco[i]);
            cp16(vb32 + (uint32_t)(kt0 % 3) * KVB + kd[i], vs + cro[i] * HD + cco[i]);
        }
        CP_COMMIT();
        ks += (size_t)BN * HD; vs += (size_t)BN * HD;
        #pragma unroll
        for (int i = 0; i < 4; i++) {
            cp16(kb32 + (uint32_t)((kt0 + 1) % 3) * KVB + kd[i], ks + cro[i] * HD + cco[i]);
            cp16(vb32 + (uint32_t)((kt0 + 1) % 3) * KVB + kd[i], vs + cro[i] * HD + cco[i]);
        }
        CP_COMMIT();
    }

    // ---- load Q tile, pre-scaled, fp32 -> fp16 ----
    #pragma unroll
    for (int it = 0; it < 16; it++) {
        int i = tid + it * NT;
        int r = i >> 4, c = (i & 15) << 2;
        float4 v = *reinterpret_cast<const float4*>(Qb + (size_t)(q0 + r) * HD + c);
        half2* dst = reinterpret_cast<half2*>(&Qs[r * KST + c]);
        dst[0] = __floats2half2_rn(v.x * QSC, v.y * QSC);
        dst[1] = __floats2half2_rn(v.z * QSC, v.w * QSC);
    }
    __syncthreads();

    // ---- Q A-fragments in registers: 2 row-blocks of 16 ----
    uint32_t qa[2][4][4];
    #pragma unroll
    for (int rb = 0; rb < 2; rb++) {
        int row = w * 32 + rb * 16 + (g & 1) * 8 + r8;
        #pragma unroll
        for (int kb = 0; kb < 4; kb++) {
            int colh = kb * 16 + (g >> 1) * 8;
            ldsm_x4(qa[rb][kb], sb32 + (uint32_t)(row * KST + colh) * 2);
        }
    }

    float o[2][8][4];
    #pragma unroll
    for (int rb = 0; rb < 2; rb++)
        #pragma unroll
        for (int a = 0; a < 8; a++)
            #pragma unroll
            for (int b = 0; b < 4; b++) o[rb][a][b] = 0.f;
    float ol[2][4];
    #pragma unroll
    for (int rb = 0; rb < 2; rb++)
        #pragma unroll
        for (int b = 0; b < 4; b++) ol[rb][b] = 0.f;

    const int qgA = q0 + w * 32 + (lane >> 2);
    const uint32_t koff = (uint32_t)(((g & 1) * 8 + r8) * KST + (g >> 1) * 8) * 2;

    for (int kt = kt0; kt <= kt1; kt++) {
        const int k0 = kt * BN;
        CP_WAIT(1);            // tile kt resident
        __syncthreads();       // buffer (kt+2)%3 free

        // ---- issue tile kt+2 ----
        {
            int kn = min(kt + 2, kt1) * BN;
            uint32_t bo = (uint32_t)((kt + 2) % 3) * KVB;
            const __half* ks = KH + (size_t)kn * HD;
            const __half* vs = VH + (size_t)kn * HD;
            #pragma unroll
            for (int i = 0; i < 4; i++) {
                cp16(kb32 + bo + kd[i], ks + cro[i] * HD + cco[i]);
                cp16(vb32 + bo + kd[i], vs + cro[i] * HD + cco[i]);
            }
            CP_COMMIT();
        }

        const uint32_t kbase = kb32 + (uint32_t)(kt % 3) * KVB;
        const uint32_t vbase = vb32 + (uint32_t)(kt % 3) * KVB;
        const bool dg = (kt >= 2 * qt);

        // ---- two 32-column halves: QK -> exp -> PV ----
        #pragma unroll
        for (int hf = 0; hf < 2; hf++) {
            float sacc[2][4][4];
            #pragma unroll
            for (int rb = 0; rb < 2; rb++)
                #pragma unroll
                for (int a = 0; a < 4; a++)
                    #pragma unroll
                    for (int b = 0; b < 4; b++) sacc[rb][a][b] = 0.f;

            #pragma unroll
            for (int kb = 0; kb < 4; kb++) {
                #pragma unroll
                for (int nbp = 0; nbp < 2; nbp++) {
                    uint32_t bk[4];
                    ldsm_x4(bk, kbase + koff +
                            (uint32_t)(((hf * 2 + nbp) * 16) * KST + kb * 16) * 2);
                    #pragma unroll
                    for (int rb = 0; rb < 2; rb++) {
                        mma16816(sacc[rb][2 * nbp],     qa[rb][kb], bk[0], bk[2]);
                        mma16816(sacc[rb][2 * nbp + 1], qa[rb][kb], bk[1], bk[3]);
                    }
                }
            }

            uint32_t ph[2][4][2];
            #pragma unroll
            for (int rb = 0; rb < 2; rb++) {
                #pragma unroll
                for (int nb = 0; nb < 4; nb++) {
                    float s0 = sacc[rb][nb][0], s1 = sacc[rb][nb][1];
                    float s2 = sacc[rb][nb][2], s3 = sacc[rb][nb][3];
                    if (dg) {
                        int c0 = k0 + hf * 32 + nb * 8 + ((lane & 3) << 1);
                        int r0 = qgA + rb * 16;
                        if (c0     > r0)     s0 = -30000.f;
                        if (c0 + 1 > r0)     s1 = -30000.f;
                        if (c0     > r0 + 8) s2 = -30000.f;
                        if (c0 + 1 > r0 + 8) s3 = -30000.f;
                    }
                    ph[rb][nb][0] = exph2(s1, s0);
                    ph[rb][nb][1] = exph2(s3, s2);
                }
            }

            #pragma unroll
            for (int kbl = 0; kbl < 2; kbl++) {
                int kbk = hf * 2 + kbl;
                #pragma unroll
                for (int nbp = 0; nbp < 4; nbp++) {
                    uint32_t bv[4];
                    ldsm_x4t(bv, vbase + koff +
                             (uint32_t)(kbk * 16 * KST + nbp * 16) * 2);
                    #pragma unroll
                    for (int rb = 0; rb < 2; rb++) {
                        uint32_t pa[4] = { ph[rb][2 * kbl][0], ph[rb][2 * kbl][1],
                                           ph[rb][2 * kbl + 1][0], ph[rb][2 * kbl + 1][1] };
                        mma16816(o[rb][2 * nbp],     pa, bv[0], bv[1]);
                        mma16816(o[rb][2 * nbp + 1], pa, bv[2], bv[3]);
                    }
                }
                uint32_t bo1[4];
                ldsm_x4t(bo1, vbase + koff + (uint32_t)(kbk * 16 * KST + 64) * 2);
                #pragma unroll
                for (int rb = 0; rb < 2; rb++) {
                    uint32_t pa[4] = { ph[rb][2 * kbl][0], ph[rb][2 * kbl][1],
                                       ph[rb][2 * kbl + 1][0], ph[rb][2 * kbl + 1][1] };
                    mma16816(ol[rb], pa, bo1[0], bo1[1]);
                }
            }
        }
    }
    CP_WAIT(0);

    if (part < 0) {
        // ---- unsplit: normalize and store directly ----
        #pragma unroll
        for (int rb = 0; rb < 2; rb++) {
            const float l0 = __shfl_sync(0xffffffffu, ol[rb][0], lane & 28);
            const float l1 = __shfl_sync(0xffffffffu, ol[rb][2], lane & 28);
            const float inv0 = 1.f / l0;
            const float inv1 = 1.f / l1;
            const int row0 = q0 + w * 32 + rb * 16 + (lane >> 2);
            const int colb = (lane & 3) << 1;
            #pragma unroll
            for (int nb = 0; nb < 8; nb++) {
                int col = nb * 8 + colb;
                *reinterpret_cast<float2*>(Ob + (size_t)row0 * HD + col) =
                    make_float2(o[rb][nb][0] * inv0, o[rb][nb][1] * inv0);
                *reinterpret_cast<float2*>(Ob + (size_t)(row0 + 8) * HD + col) =
                    make_float2(o[rb][nb][2] * inv1, o[rb][nb][3] * inv1);
            }
        }
    } else {
        // ---- split: write unnormalized partials + row sums ----
        const int sid = (bh * 8 + (qt - 8)) * 2 + part;
        float* op = OPg + (size_t)sid * (BM * HD);
        float* lp = LPg + (size_t)sid * BM;
        #pragma unroll
        for (int rb = 0; rb < 2; rb++) {
            const int row0 = w * 32 + rb * 16 + (lane >> 2);
            const int colb = (lane & 3) << 1;
            #pragma unroll
            for (int nb = 0; nb < 8; nb++) {
                int col = nb * 8 + colb;
                *reinterpret_cast<float2*>(op + row0 * HD + col) =
                    make_float2(o[rb][nb][0], o[rb][nb][1]);
                *reinterpret_cast<float2*>(op + (row0 + 8) * HD + col) =
                    make_float2(o[rb][nb][2], o[rb][nb][3]);
            }
            if ((lane & 3) == 0) {
                lp[row0]     = ol[rb][0];
                lp[row0 + 8] = ol[rb][2];
            }
        }
    }
}

// ---- combine: O = (P0 + P1) / (l0 + l1) for split q-tiles (qt 8..15) ----
__global__ __launch_bounds__(128)
void fa_combine(float* __restrict__ O) {
    int t = blockIdx.x * 128 + threadIdx.x;
    int e = t * 8;
    int rq  = e >> 13;
    int rem = e & 8191;
    int row = rem >> 6;
    float l0 = LPg[(rq * 2 + 0) * BM + row];
    float l1 = LPg[(rq * 2 + 1) * BM + row];
    float inv = 1.f / (l0 + l1);
    const float4* p0 = reinterpret_cast<const float4*>(OPg + (size_t)(rq * 2 + 0) * (BM * HD) + rem);
    const float4* p1 = reinterpret_cast<const float4*>(OPg + (size_t)(rq * 2 + 1) * (BM * HD) + rem);
    int bh = rq >> 3, qt = (rq & 7) + 8;
    float* out = O + (size_t)bh * S_LEN * HD + (size_t)qt * BM * HD + rem;
    float4 a = p0[0], b = p1[0];
    reinterpret_cast<float4*>(out)[0] =
        make_float4((a.x + b.x) * inv, (a.y + b.y) * inv, (a.z + b.z) * inv, (a.w + b.w) * inv);
    a = p0[1]; b = p1[1];
    reinterpret_cast<float4*>(out)[1] =
        make_float4((a.x + b.x) * inv, (a.y + b.y) * inv, (a.z + b.z) * inv, (a.w + b.w) * inv);
}

extern "C" void kernel_launch(void* const* d_in, const int* in_sizes, int n_in,
                              void* d_out, int out_size) {
    const float* Q = (const float*)d_in[0];
    const float* K = (const float*)d_in[1];
    const float* V = (const float*)d_in[2];
    float* O = (float*)d_out;
    (void)in_sizes; (void)n_in; (void)out_size;

    conv_kv<<<TOT / (256 * 16), 256>>>(K, V);    // high-MLP prepass

    cudaFuncSetAttribute(fa_hmma13, cudaFuncAttributeMaxDynamicSharedMemorySize, SM_TOTAL);
    dim3 grid(32, 24);                 // x = bh, y = task (heavy-first, r11 table)
    fa_hmma13<<<grid, NT, SM_TOTAL>>>(Q, O);

    fa_combine<<<2048, 128>>>(O);
}